// round 10
// baseline (speedup 1.0000x reference)
#include <cuda_runtime.h>
#include <cuda_bf16.h>
#include <math.h>
#include <stdint.h>

// Problem constants
#define B_  8
#define N_  2048
#define F_  256
#define ROWS (B_ * N_)            // 16384
#define OUT_ELEMS ((size_t)B_ * N_ * F_)   // 4,194,304

// Scratch (device globals — no allocation allowed)
__device__ __nv_bfloat16 g_Whb[(size_t)B_ * N_ * F_];        // 8 MB bf16 [b][node m][feat f]
__device__ __nv_bfloat16 g_att_bf[(size_t)B_ * N_ * N_];     // 67 MB bf16 [b][n][m]
__device__ __align__(16) float g_e1[ROWS];
__device__ __align__(16) float g_e2[ROWS];
__device__ __align__(16) float g_w1[F_];
__device__ __align__(16) float g_w2[F_];

// ---------------------------------------------------------------------------
// MMA / ldmatrix / cp.async helpers
// ---------------------------------------------------------------------------
__device__ __forceinline__ void mma_tf32(float* c, const uint32_t* a, const uint32_t* b) {
    asm volatile(
        "mma.sync.aligned.m16n8k8.row.col.f32.tf32.tf32.f32 "
        "{%0,%1,%2,%3}, {%4,%5,%6,%7}, {%8,%9}, {%0,%1,%2,%3};\n"
        : "+f"(c[0]), "+f"(c[1]), "+f"(c[2]), "+f"(c[3])
        : "r"(a[0]), "r"(a[1]), "r"(a[2]), "r"(a[3]), "r"(b[0]), "r"(b[1]));
}

__device__ __forceinline__ void mma_bf16(float* c, const uint32_t* a, const uint32_t* b) {
    asm volatile(
        "mma.sync.aligned.m16n8k16.row.col.f32.bf16.bf16.f32 "
        "{%0,%1,%2,%3}, {%4,%5,%6,%7}, {%8,%9}, {%0,%1,%2,%3};\n"
        : "+f"(c[0]), "+f"(c[1]), "+f"(c[2]), "+f"(c[3])
        : "r"(a[0]), "r"(a[1]), "r"(a[2]), "r"(a[3]), "r"(b[0]), "r"(b[1]));
}

__device__ __forceinline__ void ldsm_x4(uint32_t& r0, uint32_t& r1, uint32_t& r2, uint32_t& r3,
                                        const void* p) {
    uint32_t a = (uint32_t)__cvta_generic_to_shared(p);
    asm volatile("ldmatrix.sync.aligned.m8n8.x4.shared.b16 {%0,%1,%2,%3}, [%4];"
                 : "=r"(r0), "=r"(r1), "=r"(r2), "=r"(r3) : "r"(a));
}
__device__ __forceinline__ void ldsm_x4_t(uint32_t& r0, uint32_t& r1, uint32_t& r2, uint32_t& r3,
                                          const void* p) {
    uint32_t a = (uint32_t)__cvta_generic_to_shared(p);
    asm volatile("ldmatrix.sync.aligned.m8n8.x4.trans.shared.b16 {%0,%1,%2,%3}, [%4];"
                 : "=r"(r0), "=r"(r1), "=r"(r2), "=r"(r3) : "r"(a));
}

__device__ __forceinline__ void cp16(void* dst, const void* src) {
    uint32_t d = (uint32_t)__cvta_generic_to_shared(dst);
    asm volatile("cp.async.cg.shared.global [%0], [%1], 16;\n" :: "r"(d), "l"(src));
}
__device__ __forceinline__ void cp_commit() {
    asm volatile("cp.async.commit_group;\n");
}
template<int NPEND> __device__ __forceinline__ void cp_wait() {
    asm volatile("cp.async.wait_group %0;\n" :: "n"(NPEND));
}

// ---------------------------------------------------------------------------
// Kernel 0: w1[r] = W[r,:]·a[:F],  w2[r] = W[r,:]·a[F:]   (W @ a, row dots)
// ---------------------------------------------------------------------------
__global__ void k_wa(const float* __restrict__ W, const float* __restrict__ a) {
    const int r = (blockIdx.x * blockDim.x + threadIdx.x) >> 5;   // 0..255
    const int lane = threadIdx.x & 31;
    if (r >= F_) return;
    const float* row = W + (size_t)r * F_;
    float s1 = 0.f, s2 = 0.f;
    #pragma unroll
    for (int f = lane; f < F_; f += 32) {
        float w = row[f];
        s1 = fmaf(w, a[f],      s1);
        s2 = fmaf(w, a[F_ + f], s2);
    }
    #pragma unroll
    for (int o = 16; o; o >>= 1) {
        s1 += __shfl_xor_sync(0xffffffffu, s1, o);
        s2 += __shfl_xor_sync(0xffffffffu, s2, o);
    }
    if (lane == 0) { g_w1[r] = s1; g_w2[r] = s2; }
}

// ---------------------------------------------------------------------------
// Kernel E: e1[r] = h[r,:]·w1, e2[r] = h[r,:]·w2   (one warp per row, exact)
// ---------------------------------------------------------------------------
__global__ void k_rowdots(const float* __restrict__ h) {
    const int gwarp = (blockIdx.x * blockDim.x + threadIdx.x) >> 5;
    const int lane = threadIdx.x & 31;
    if (gwarp >= ROWS) return;
    const float4* row = (const float4*)(h + (size_t)gwarp * F_);
    const float4* w1v = (const float4*)g_w1;
    const float4* w2v = (const float4*)g_w2;
    float s1 = 0.f, s2 = 0.f;
    #pragma unroll
    for (int f4 = lane; f4 < F_ / 4; f4 += 32) {
        float4 v = row[f4], w1 = w1v[f4], w2 = w2v[f4];
        s1 = fmaf(v.x, w1.x, fmaf(v.y, w1.y, fmaf(v.z, w1.z, fmaf(v.w, w1.w, s1))));
        s2 = fmaf(v.x, w2.x, fmaf(v.y, w2.y, fmaf(v.z, w2.z, fmaf(v.w, w2.w, s2))));
    }
    #pragma unroll
    for (int o = 16; o; o >>= 1) {
        s1 += __shfl_xor_sync(0xffffffffu, s1, o);
        s2 += __shfl_xor_sync(0xffffffffu, s2, o);
    }
    if (lane == 0) { g_e1[gwarp] = s1; g_e2[gwarp] = s2; }
}

// ---------------------------------------------------------------------------
// Kernel 1: Whb(bf16) = h @ W via single-pass TF32 MMA (tile 128x128x32).
// ---------------------------------------------------------------------------
#define STAGE_FLOATS 8960
#define A_OFF 0
#define B_OFF 4608
#define SMEM_BYTES_K1 (2 * STAGE_FLOATS * 4)   // 71680

__global__ __launch_bounds__(256, 2) void k_gemm_wh(const float* __restrict__ h,
                                                    const float* __restrict__ W) {
    extern __shared__ float dsm[];
    const int bx = blockIdx.x;
    const int by = blockIdx.y;
    const int tid = threadIdx.x;
    const int lane = tid & 31, wid = tid >> 5;
    const int warp_m = wid & 3, warp_n = wid >> 2;
    const int gid = lane >> 2, tig = lane & 3;

    const float* A  = h + (size_t)(by * 128) * F_;
    const float* Bg = W + bx * 128;

    float acc[2][8][4];
    #pragma unroll
    for (int mt = 0; mt < 2; mt++)
        #pragma unroll
        for (int j = 0; j < 8; j++)
            #pragma unroll
            for (int q = 0; q < 4; q++) acc[mt][j][q] = 0.f;

    {
        float* As = dsm + A_OFF;
        float* Bs = dsm + B_OFF;
        #pragma unroll
        for (int i = 0; i < 4; i++) {
            int flat = tid + i * 256, row = flat >> 3, c4 = flat & 7;
            cp16(&As[row * 36 + c4 * 4], A + (size_t)row * F_ + c4 * 4);
        }
        #pragma unroll
        for (int i = 0; i < 4; i++) {
            int flat = tid + i * 256, kr = flat >> 5, c4 = flat & 31;
            cp16(&Bs[kr * 136 + c4 * 4], Bg + (size_t)kr * F_ + c4 * 4);
        }
        cp_commit();
    }

    const int NT = F_ / 32;   // 8
    for (int kt = 0; kt < NT; kt++) {
        const int cur = kt & 1;
        if (kt + 1 < NT) {
            const int k0 = (kt + 1) * 32;
            float* As = dsm + (1 - cur) * STAGE_FLOATS + A_OFF;
            float* Bs = dsm + (1 - cur) * STAGE_FLOATS + B_OFF;
            #pragma unroll
            for (int i = 0; i < 4; i++) {
                int flat = tid + i * 256, row = flat >> 3, c4 = flat & 7;
                cp16(&As[row * 36 + c4 * 4], A + (size_t)row * F_ + k0 + c4 * 4);
            }
            #pragma unroll
            for (int i = 0; i < 4; i++) {
                int flat = tid + i * 256, kr = flat >> 5, c4 = flat & 31;
                cp16(&Bs[kr * 136 + c4 * 4], Bg + (size_t)(k0 + kr) * F_ + c4 * 4);
            }
            cp_commit();
            cp_wait<1>();
        } else {
            cp_wait<0>();
        }
        __syncthreads();

        const float* As = dsm + cur * STAGE_FLOATS + A_OFF;
        const float* Bs = dsm + cur * STAGE_FLOATS + B_OFF;

        #pragma unroll
        for (int kk = 0; kk < 32; kk += 8) {
            uint32_t afr[2][4];
            #pragma unroll
            for (int mt = 0; mt < 2; mt++) {
                int r = warp_m * 32 + mt * 16 + gid;
                afr[mt][0] = __float_as_uint(As[ r      * 36 + kk + tig    ]);
                afr[mt][1] = __float_as_uint(As[(r + 8) * 36 + kk + tig    ]);
                afr[mt][2] = __float_as_uint(As[ r      * 36 + kk + tig + 4]);
                afr[mt][3] = __float_as_uint(As[(r + 8) * 36 + kk + tig + 4]);
            }
            uint32_t bfr[8][2];
            #pragma unroll
            for (int j = 0; j < 8; j++) {
                int n = warp_n * 64 + j * 8 + gid;
                bfr[j][0] = __float_as_uint(Bs[(kk + tig    ) * 136 + n]);
                bfr[j][1] = __float_as_uint(Bs[(kk + tig + 4) * 136 + n]);
            }
            #pragma unroll
            for (int mt = 0; mt < 2; mt++)
                #pragma unroll
                for (int j = 0; j < 8; j++)
                    mma_tf32(acc[mt][j], afr[mt], bfr[j]);
        }
        __syncthreads();
    }

    #pragma unroll
    for (int mt = 0; mt < 2; mt++) {
        #pragma unroll
        for (int j = 0; j < 8; j++) {
            const int m0 = by * 128 + warp_m * 32 + mt * 16 + gid;
            const int n  = bx * 128 + warp_n * 64 + j * 8 + tig * 2;
            *(__nv_bfloat162*)(g_Whb + (size_t) m0      * F_ + n) =
                __floats2bfloat162_rn(acc[mt][j][0], acc[mt][j][1]);
            *(__nv_bfloat162*)(g_Whb + (size_t)(m0 + 8) * F_ + n) =
                __floats2bfloat162_rn(acc[mt][j][2], acc[mt][j][3]);
        }
    }
}

// ---------------------------------------------------------------------------
// Kernel 3: masked leaky-relu + softmax — register-resident.
// rowoff selects the batch-half (pipelined with k4).
// ---------------------------------------------------------------------------
__global__ __launch_bounds__(256) void k_softmax(const int* __restrict__ adj,
                                                 float* __restrict__ att,
                                                 int rowoff) {
    const int r = blockIdx.x + rowoff;
    const int b = r >> 11;
    __shared__ float red[8];

    const int4*   arow4 = (const int4*)(adj + (size_t)r * N_);
    const float4* e2b4  = (const float4*)(g_e2 + b * N_);
    const float E1 = g_e1[r];
    const int tid = threadIdx.x, lane = tid & 31, wid = tid >> 5;

    const int m4a = tid;
    const int m4b = tid + 256;

    int4   ad0 = arow4[m4a], ad1 = arow4[m4b];
    float4 e20 = e2b4[m4a],  e21 = e2b4[m4b];

    float v[8];
    {
        float x;
        x = E1 + e20.x; x = x > 0.f ? x : 0.2f * x; v[0] = ad0.x > 0 ? __expf(x) : 0.f;
        x = E1 + e20.y; x = x > 0.f ? x : 0.2f * x; v[1] = ad0.y > 0 ? __expf(x) : 0.f;
        x = E1 + e20.z; x = x > 0.f ? x : 0.2f * x; v[2] = ad0.z > 0 ? __expf(x) : 0.f;
        x = E1 + e20.w; x = x > 0.f ? x : 0.2f * x; v[3] = ad0.w > 0 ? __expf(x) : 0.f;
        x = E1 + e21.x; x = x > 0.f ? x : 0.2f * x; v[4] = ad1.x > 0 ? __expf(x) : 0.f;
        x = E1 + e21.y; x = x > 0.f ? x : 0.2f * x; v[5] = ad1.y > 0 ? __expf(x) : 0.f;
        x = E1 + e21.z; x = x > 0.f ? x : 0.2f * x; v[6] = ad1.z > 0 ? __expf(x) : 0.f;
        x = E1 + e21.w; x = x > 0.f ? x : 0.2f * x; v[7] = ad1.w > 0 ? __expf(x) : 0.f;
    }
    float lsum = ((v[0] + v[1]) + (v[2] + v[3])) + ((v[4] + v[5]) + (v[6] + v[7]));
    #pragma unroll
    for (int o = 16; o; o >>= 1) lsum += __shfl_xor_sync(0xffffffffu, lsum, o);
    if (lane == 0) red[wid] = lsum;
    __syncthreads();
    if (tid == 0) {
        float t = 0.f;
        #pragma unroll
        for (int i = 0; i < 8; i++) t += red[i];
        red[0] = 1.0f / t;
    }
    __syncthreads();
    const float inv = red[0];

    float4* orow4 = (float4*)(att + (size_t)r * N_);
    __nv_bfloat162* brow2 = (__nv_bfloat162*)(g_att_bf + (size_t)r * N_);
    float4 o0 = make_float4(v[0] * inv, v[1] * inv, v[2] * inv, v[3] * inv);
    float4 o1 = make_float4(v[4] * inv, v[5] * inv, v[6] * inv, v[7] * inv);
    orow4[m4a] = o0;
    orow4[m4b] = o1;
    brow2[m4a * 2    ] = __floats2bfloat162_rn(o0.x, o0.y);
    brow2[m4a * 2 + 1] = __floats2bfloat162_rn(o0.z, o0.w);
    brow2[m4b * 2    ] = __floats2bfloat162_rn(o1.x, o1.y);
    brow2[m4b * 2 + 1] = __floats2bfloat162_rn(o1.z, o1.w);
}

// ---------------------------------------------------------------------------
// Kernel 4: h_prime = attention @ Wh, bf16 m16n8k16 mma.sync.
//   Tile 128x128, K-chunk 64, 3-stage cp.async ring. bz0 = batch offset.
// ---------------------------------------------------------------------------
#define KCHUNK 64
#define HSTRIDE 72                        // A smem row: 64 bf16 + 8 pad (144 B)
#define BSTRIDE_H 136                     // B smem row: 128 bf16 + 8 pad (272 B)
#define A_ELEMS (128 * HSTRIDE)           // 9216
#define STAGE_H (A_ELEMS + KCHUNK * BSTRIDE_H)   // 17920 bf16
#define K4_STAGES 3
#define SMEM_BYTES_K4 (K4_STAGES * STAGE_H * 2)   // 107520 B

__device__ __forceinline__ void k4_load_stage(__nv_bfloat16* stage,
                                              const __nv_bfloat16* A,
                                              const __nv_bfloat16* Bw,
                                              int k0, int tid) {
    __nv_bfloat16* As = stage;
    __nv_bfloat16* Bs = stage + A_ELEMS;
    #pragma unroll
    for (int i = 0; i < 4; i++) {                 // A: 128 rows x 8 x 16B
        int flat = tid + i * 256, row = flat >> 3, c = flat & 7;
        cp16(&As[row * HSTRIDE + c * 8], A + (size_t)row * N_ + k0 + c * 8);
    }
    #pragma unroll
    for (int i = 0; i < 4; i++) {                 // B: 64 rows x 16 x 16B
        int flat = tid + i * 256, kr = flat >> 4, c = flat & 15;
        cp16(&Bs[kr * BSTRIDE_H + c * 8], Bw + (size_t)(k0 + kr) * F_ + c * 8);
    }
}

__global__ __launch_bounds__(256, 2) void k_gemm_av_bf16(const float* __restrict__ h,
                                                         float* __restrict__ out,
                                                         int bz0) {
    extern __shared__ __nv_bfloat16 hsm[];
    const int bz = blockIdx.z + bz0;
    const int bx = blockIdx.x;   // 0..1 (n tile of 128)
    const int by = blockIdx.y;   // 0..15 (m tile of 128)
    const int tid = threadIdx.x;
    const int lane = tid & 31, wid = tid >> 5;
    const int warp_m = wid & 3, warp_n = wid >> 2;
    const int gid = lane >> 2, tig = lane & 3;

    const __nv_bfloat16* A  = g_att_bf + (size_t)bz * N_ * N_ + (size_t)(by * 128) * N_;
    const __nv_bfloat16* Bw = g_Whb   + (size_t)bz * N_ * F_ + bx * 128;

    float acc[2][8][4];
    #pragma unroll
    for (int mt = 0; mt < 2; mt++)
        #pragma unroll
        for (int j = 0; j < 8; j++)
            #pragma unroll
            for (int q = 0; q < 4; q++) acc[mt][j][q] = 0.f;

    // prologue: stages 0,1 = chunks 0,1
    k4_load_stage(hsm,           A, Bw, 0,      tid); cp_commit();
    k4_load_stage(hsm + STAGE_H, A, Bw, KCHUNK, tid); cp_commit();

    // ldmatrix lane offsets
    const int a_mat = lane >> 3, a_r = lane & 7;
    const int a_row_off = ((a_mat & 1) << 3) + a_r;
    const int a_k_off   = (a_mat >> 1) << 3;
    const int b_k_lane  = lane & 15;
    const int b_n_half  = (lane >> 4) << 3;

    const int NT = N_ / KCHUNK;   // 32
    int s = 0;
    for (int kt = 0; kt < NT; kt++) {
        cp_wait<1>();
        __syncthreads();

        if (kt + 2 < NT) {
            int sn = s + 2; if (sn >= K4_STAGES) sn -= K4_STAGES;
            k4_load_stage(hsm + sn * STAGE_H, A, Bw, (kt + 2) * KCHUNK, tid);
        }
        cp_commit();

        const __nv_bfloat16* As = hsm + s * STAGE_H;
        const __nv_bfloat16* Bs = As + A_ELEMS;

        #pragma unroll
        for (int kk = 0; kk < KCHUNK; kk += 16) {
            uint32_t af[2][4];
            #pragma unroll
            for (int mt = 0; mt < 2; mt++) {
                const __nv_bfloat16* p =
                    As + (warp_m * 32 + mt * 16 + a_row_off) * HSTRIDE + kk + a_k_off;
                ldsm_x4(af[mt][0], af[mt][1], af[mt][2], af[mt][3], p);
            }
            uint32_t bf[8][2];
            #pragma unroll
            for (int jp = 0; jp < 4; jp++) {
                const __nv_bfloat16* p =
                    Bs + (kk + b_k_lane) * BSTRIDE_H + warp_n * 64 + jp * 16 + b_n_half;
                ldsm_x4_t(bf[2*jp][0], bf[2*jp][1], bf[2*jp+1][0], bf[2*jp+1][1], p);
            }
            #pragma unroll
            for (int mt = 0; mt < 2; mt++)
                #pragma unroll
                for (int j = 0; j < 8; j++)
                    mma_bf16(acc[mt][j], af[mt], bf[j]);
        }
        if (++s >= K4_STAGES) s = 0;
        __syncthreads();
    }

    // epilogue: out = h + elu(h_prime)
    const size_t base = (size_t)bz * N_ * F_;
    #pragma unroll
    for (int mt = 0; mt < 2; mt++) {
        #pragma unroll
        for (int j = 0; j < 8; j++) {
            const int m0 = by * 128 + warp_m * 32 + mt * 16 + gid;
            const int n  = bx * 128 + warp_n * 64 + j * 8 + tig * 2;
            {
                const size_t idx = base + (size_t)m0 * F_ + n;
                float c0 = acc[mt][j][0], c1 = acc[mt][j][1];
                float e0 = c0 > 0.f ? c0 : expm1f(c0);
                float e1 = c1 > 0.f ? c1 : expm1f(c1);
                float2 hv = *(const float2*)(h + idx);
                *(float2*)(out + idx) = make_float2(hv.x + e0, hv.y + e1);
            }
            {
                const size_t idx = base + (size_t)(m0 + 8) * F_ + n;
                float c2 = acc[mt][j][2], c3 = acc[mt][j][3];
                float e2 = c2 > 0.f ? c2 : expm1f(c2);
                float e3 = c3 > 0.f ? c3 : expm1f(c3);
                float2 hv = *(const float2*)(h + idx);
                *(float2*)(out + idx) = make_float2(hv.x + e2, hv.y + e3);
            }
        }
    }
}

// ---------------------------------------------------------------------------
extern "C" void kernel_launch(void* const* d_in, const int* in_sizes, int n_in,
                              void* d_out, int out_size) {
    const float* h   = (const float*)d_in[0];
    const int*   adj = (const int*)  d_in[1];
    const float* W   = (const float*)d_in[2];
    const float* a   = (const float*)d_in[3];
    float* out = (float*)d_out;
    float* att = out + OUT_ELEMS;

    cudaFuncSetAttribute(k_gemm_wh,      cudaFuncAttributeMaxDynamicSharedMemorySize, SMEM_BYTES_K1);
    cudaFuncSetAttribute(k_gemm_av_bf16, cudaFuncAttributeMaxDynamicSharedMemorySize, SMEM_BYTES_K4);

    // Host-side stream/event objects only (no device memory). Not destroyed:
    // destroying a capture-forked stream before EndCapture invalidates capture,
    // and kernel_launch runs exactly twice outside timing, so the leak is bounded.
    cudaStream_t s2;
    cudaStreamCreateWithFlags(&s2, cudaStreamNonBlocking);
    cudaEvent_t eFork, eS1, eS2, eDone;
    cudaEventCreateWithFlags(&eFork, cudaEventDisableTiming);
    cudaEventCreateWithFlags(&eS1,   cudaEventDisableTiming);
    cudaEventCreateWithFlags(&eS2,   cudaEventDisableTiming);
    cudaEventCreateWithFlags(&eDone, cudaEventDisableTiming);

    // fork side stream
    cudaEventRecord(eFork, 0);
    cudaStreamWaitEvent(s2, eFork, 0);
    // side branch: 1. Whb(bf16) = h @ W  (independent of score path)
    k_gemm_wh<<<dim3(2, ROWS / 128), 256, SMEM_BYTES_K1, s2>>>(h, W);

    // main branch (critical path):
    k_wa<<<F_ / 8, 256>>>(W, a);
    k_rowdots<<<ROWS / 8, 256>>>(h);
    // softmax half 1 (batches 0-3)
    k_softmax<<<ROWS / 2, 256>>>(adj, att, 0);
    cudaEventRecord(eS1, 0);
    // softmax half 2 (batches 4-7) — overlaps k4 half 1 on s2
    k_softmax<<<ROWS / 2, 256>>>(adj, att, ROWS / 2);
    cudaEventRecord(eS2, 0);

    // side stream: k4 halves (queue behind k_gemm_wh -> Whb dependency ordered)
    cudaStreamWaitEvent(s2, eS1, 0);
    k_gemm_av_bf16<<<dim3(2, N_ / 128, B_ / 2), 256, SMEM_BYTES_K4, s2>>>(h, out, 0);
    cudaStreamWaitEvent(s2, eS2, 0);
    k_gemm_av_bf16<<<dim3(2, N_ / 128, B_ / 2), 256, SMEM_BYTES_K4, s2>>>(h, out, B_ / 2);

    // join side stream back into the capture origin stream
    cudaEventRecord(eDone, s2);
    cudaStreamWaitEvent(0, eDone, 0);
}

// round 11
// speedup vs baseline: 1.1829x; 1.1829x over previous
#include <cuda_runtime.h>
#include <cuda_bf16.h>
#include <cuda_fp16.h>
#include <math.h>
#include <stdint.h>

// Problem constants
#define B_  8
#define N_  2048
#define F_  256
#define ROWS (B_ * N_)            // 16384
#define OUT_ELEMS ((size_t)B_ * N_ * F_)   // 4,194,304

// Scratch (device globals — no allocation allowed)
__device__ __half g_Whh[(size_t)B_ * N_ * F_];        // 8 MB fp16 [b][node m][feat f]
__device__ __half g_att_h[(size_t)B_ * N_ * N_];      // 67 MB fp16 [b][n][m]
__device__ __align__(16) float g_e1[ROWS];
__device__ __align__(16) float g_e2[ROWS];
__device__ __align__(16) float g_w1[F_];
__device__ __align__(16) float g_w2[F_];

// ---------------------------------------------------------------------------
// MMA / ldmatrix / cp.async helpers
// ---------------------------------------------------------------------------
__device__ __forceinline__ void mma_tf32(float* c, const uint32_t* a, const uint32_t* b) {
    asm volatile(
        "mma.sync.aligned.m16n8k8.row.col.f32.tf32.tf32.f32 "
        "{%0,%1,%2,%3}, {%4,%5,%6,%7}, {%8,%9}, {%0,%1,%2,%3};\n"
        : "+f"(c[0]), "+f"(c[1]), "+f"(c[2]), "+f"(c[3])
        : "r"(a[0]), "r"(a[1]), "r"(a[2]), "r"(a[3]), "r"(b[0]), "r"(b[1]));
}

// fp16 inputs, fp16 accumulators (2 regs = 4 halves)
__device__ __forceinline__ void mma_f16(uint32_t* c, const uint32_t* a, const uint32_t* b) {
    asm volatile(
        "mma.sync.aligned.m16n8k16.row.col.f16.f16.f16.f16 "
        "{%0,%1}, {%2,%3,%4,%5}, {%6,%7}, {%0,%1};\n"
        : "+r"(c[0]), "+r"(c[1])
        : "r"(a[0]), "r"(a[1]), "r"(a[2]), "r"(a[3]), "r"(b[0]), "r"(b[1]));
}

__device__ __forceinline__ void ldsm_x4(uint32_t& r0, uint32_t& r1, uint32_t& r2, uint32_t& r3,
                                        const void* p) {
    uint32_t a = (uint32_t)__cvta_generic_to_shared(p);
    asm volatile("ldmatrix.sync.aligned.m8n8.x4.shared.b16 {%0,%1,%2,%3}, [%4];"
                 : "=r"(r0), "=r"(r1), "=r"(r2), "=r"(r3) : "r"(a));
}
__device__ __forceinline__ void ldsm_x4_t(uint32_t& r0, uint32_t& r1, uint32_t& r2, uint32_t& r3,
                                          const void* p) {
    uint32_t a = (uint32_t)__cvta_generic_to_shared(p);
    asm volatile("ldmatrix.sync.aligned.m8n8.x4.trans.shared.b16 {%0,%1,%2,%3}, [%4];"
                 : "=r"(r0), "=r"(r1), "=r"(r2), "=r"(r3) : "r"(a));
}

__device__ __forceinline__ void cp16(void* dst, const void* src) {
    uint32_t d = (uint32_t)__cvta_generic_to_shared(dst);
    asm volatile("cp.async.cg.shared.global [%0], [%1], 16;\n" :: "r"(d), "l"(src));
}
__device__ __forceinline__ void cp_commit() {
    asm volatile("cp.async.commit_group;\n");
}
template<int NPEND> __device__ __forceinline__ void cp_wait() {
    asm volatile("cp.async.wait_group %0;\n" :: "n"(NPEND));
}

// ---------------------------------------------------------------------------
// Kernel 0: w1[r] = W[r,:]·a[:F],  w2[r] = W[r,:]·a[F:]   (W @ a, row dots)
// ---------------------------------------------------------------------------
__global__ void k_wa(const float* __restrict__ W, const float* __restrict__ a) {
    const int r = (blockIdx.x * blockDim.x + threadIdx.x) >> 5;   // 0..255
    const int lane = threadIdx.x & 31;
    if (r >= F_) return;
    const float* row = W + (size_t)r * F_;
    float s1 = 0.f, s2 = 0.f;
    #pragma unroll
    for (int f = lane; f < F_; f += 32) {
        float w = row[f];
        s1 = fmaf(w, a[f],      s1);
        s2 = fmaf(w, a[F_ + f], s2);
    }
    #pragma unroll
    for (int o = 16; o; o >>= 1) {
        s1 += __shfl_xor_sync(0xffffffffu, s1, o);
        s2 += __shfl_xor_sync(0xffffffffu, s2, o);
    }
    if (lane == 0) { g_w1[r] = s1; g_w2[r] = s2; }
}

// ---------------------------------------------------------------------------
// Kernel E: e1[r] = h[r,:]·w1, e2[r] = h[r,:]·w2   (one warp per row, exact)
// ---------------------------------------------------------------------------
__global__ void k_rowdots(const float* __restrict__ h) {
    const int gwarp = (blockIdx.x * blockDim.x + threadIdx.x) >> 5;
    const int lane = threadIdx.x & 31;
    if (gwarp >= ROWS) return;
    const float4* row = (const float4*)(h + (size_t)gwarp * F_);
    const float4* w1v = (const float4*)g_w1;
    const float4* w2v = (const float4*)g_w2;
    float s1 = 0.f, s2 = 0.f;
    #pragma unroll
    for (int f4 = lane; f4 < F_ / 4; f4 += 32) {
        float4 v = row[f4], w1 = w1v[f4], w2 = w2v[f4];
        s1 = fmaf(v.x, w1.x, fmaf(v.y, w1.y, fmaf(v.z, w1.z, fmaf(v.w, w1.w, s1))));
        s2 = fmaf(v.x, w2.x, fmaf(v.y, w2.y, fmaf(v.z, w2.z, fmaf(v.w, w2.w, s2))));
    }
    #pragma unroll
    for (int o = 16; o; o >>= 1) {
        s1 += __shfl_xor_sync(0xffffffffu, s1, o);
        s2 += __shfl_xor_sync(0xffffffffu, s2, o);
    }
    if (lane == 0) { g_e1[gwarp] = s1; g_e2[gwarp] = s2; }
}

// ---------------------------------------------------------------------------
// Kernel 1: Whh(fp16) = h @ W via single-pass TF32 MMA (tile 128x128x32).
// ---------------------------------------------------------------------------
#define STAGE_FLOATS 8960
#define A_OFF 0
#define B_OFF 4608
#define SMEM_BYTES_K1 (2 * STAGE_FLOATS * 4)   // 71680

__global__ __launch_bounds__(256, 2) void k_gemm_wh(const float* __restrict__ h,
                                                    const float* __restrict__ W) {
    extern __shared__ float dsm[];
    const int bx = blockIdx.x;
    const int by = blockIdx.y;
    const int tid = threadIdx.x;
    const int lane = tid & 31, wid = tid >> 5;
    const int warp_m = wid & 3, warp_n = wid >> 2;
    const int gid = lane >> 2, tig = lane & 3;

    const float* A  = h + (size_t)(by * 128) * F_;
    const float* Bg = W + bx * 128;

    float acc[2][8][4];
    #pragma unroll
    for (int mt = 0; mt < 2; mt++)
        #pragma unroll
        for (int j = 0; j < 8; j++)
            #pragma unroll
            for (int q = 0; q < 4; q++) acc[mt][j][q] = 0.f;

    {
        float* As = dsm + A_OFF;
        float* Bs = dsm + B_OFF;
        #pragma unroll
        for (int i = 0; i < 4; i++) {
            int flat = tid + i * 256, row = flat >> 3, c4 = flat & 7;
            cp16(&As[row * 36 + c4 * 4], A + (size_t)row * F_ + c4 * 4);
        }
        #pragma unroll
        for (int i = 0; i < 4; i++) {
            int flat = tid + i * 256, kr = flat >> 5, c4 = flat & 31;
            cp16(&Bs[kr * 136 + c4 * 4], Bg + (size_t)kr * F_ + c4 * 4);
        }
        cp_commit();
    }

    const int NT = F_ / 32;   // 8
    for (int kt = 0; kt < NT; kt++) {
        const int cur = kt & 1;
        if (kt + 1 < NT) {
            const int k0 = (kt + 1) * 32;
            float* As = dsm + (1 - cur) * STAGE_FLOATS + A_OFF;
            float* Bs = dsm + (1 - cur) * STAGE_FLOATS + B_OFF;
            #pragma unroll
            for (int i = 0; i < 4; i++) {
                int flat = tid + i * 256, row = flat >> 3, c4 = flat & 7;
                cp16(&As[row * 36 + c4 * 4], A + (size_t)row * F_ + k0 + c4 * 4);
            }
            #pragma unroll
            for (int i = 0; i < 4; i++) {
                int flat = tid + i * 256, kr = flat >> 5, c4 = flat & 31;
                cp16(&Bs[kr * 136 + c4 * 4], Bg + (size_t)(k0 + kr) * F_ + c4 * 4);
            }
            cp_commit();
            cp_wait<1>();
        } else {
            cp_wait<0>();
        }
        __syncthreads();

        const float* As = dsm + cur * STAGE_FLOATS + A_OFF;
        const float* Bs = dsm + cur * STAGE_FLOATS + B_OFF;

        #pragma unroll
        for (int kk = 0; kk < 32; kk += 8) {
            uint32_t afr[2][4];
            #pragma unroll
            for (int mt = 0; mt < 2; mt++) {
                int r = warp_m * 32 + mt * 16 + gid;
                afr[mt][0] = __float_as_uint(As[ r      * 36 + kk + tig    ]);
                afr[mt][1] = __float_as_uint(As[(r + 8) * 36 + kk + tig    ]);
                afr[mt][2] = __float_as_uint(As[ r      * 36 + kk + tig + 4]);
                afr[mt][3] = __float_as_uint(As[(r + 8) * 36 + kk + tig + 4]);
            }
            uint32_t bfr[8][2];
            #pragma unroll
            for (int j = 0; j < 8; j++) {
                int n = warp_n * 64 + j * 8 + gid;
                bfr[j][0] = __float_as_uint(Bs[(kk + tig    ) * 136 + n]);
                bfr[j][1] = __float_as_uint(Bs[(kk + tig + 4) * 136 + n]);
            }
            #pragma unroll
            for (int mt = 0; mt < 2; mt++)
                #pragma unroll
                for (int j = 0; j < 8; j++)
                    mma_tf32(acc[mt][j], afr[mt], bfr[j]);
        }
        __syncthreads();
    }

    #pragma unroll
    for (int mt = 0; mt < 2; mt++) {
        #pragma unroll
        for (int j = 0; j < 8; j++) {
            const int m0 = by * 128 + warp_m * 32 + mt * 16 + gid;
            const int n  = bx * 128 + warp_n * 64 + j * 8 + tig * 2;
            *(__half2*)(g_Whh + (size_t) m0      * F_ + n) =
                __floats2half2_rn(acc[mt][j][0], acc[mt][j][1]);
            *(__half2*)(g_Whh + (size_t)(m0 + 8) * F_ + n) =
                __floats2half2_rn(acc[mt][j][2], acc[mt][j][3]);
        }
    }
}

// ---------------------------------------------------------------------------
// Kernel 3: masked leaky-relu + softmax — register-resident.
// Writes fp32 attention to d_out AND fp16 copy to g_att_h.
// ---------------------------------------------------------------------------
__global__ __launch_bounds__(256) void k_softmax(const int* __restrict__ adj,
                                                 float* __restrict__ att) {
    const int r = blockIdx.x;
    const int b = r >> 11;
    __shared__ float red[8];

    const int4*   arow4 = (const int4*)(adj + (size_t)r * N_);
    const float4* e2b4  = (const float4*)(g_e2 + b * N_);
    const float E1 = g_e1[r];
    const int tid = threadIdx.x, lane = tid & 31, wid = tid >> 5;

    const int m4a = tid;
    const int m4b = tid + 256;

    int4   ad0 = arow4[m4a], ad1 = arow4[m4b];
    float4 e20 = e2b4[m4a],  e21 = e2b4[m4b];

    float v[8];
    {
        float x;
        x = E1 + e20.x; x = x > 0.f ? x : 0.2f * x; v[0] = ad0.x > 0 ? __expf(x) : 0.f;
        x = E1 + e20.y; x = x > 0.f ? x : 0.2f * x; v[1] = ad0.y > 0 ? __expf(x) : 0.f;
        x = E1 + e20.z; x = x > 0.f ? x : 0.2f * x; v[2] = ad0.z > 0 ? __expf(x) : 0.f;
        x = E1 + e20.w; x = x > 0.f ? x : 0.2f * x; v[3] = ad0.w > 0 ? __expf(x) : 0.f;
        x = E1 + e21.x; x = x > 0.f ? x : 0.2f * x; v[4] = ad1.x > 0 ? __expf(x) : 0.f;
        x = E1 + e21.y; x = x > 0.f ? x : 0.2f * x; v[5] = ad1.y > 0 ? __expf(x) : 0.f;
        x = E1 + e21.z; x = x > 0.f ? x : 0.2f * x; v[6] = ad1.z > 0 ? __expf(x) : 0.f;
        x = E1 + e21.w; x = x > 0.f ? x : 0.2f * x; v[7] = ad1.w > 0 ? __expf(x) : 0.f;
    }
    float lsum = ((v[0] + v[1]) + (v[2] + v[3])) + ((v[4] + v[5]) + (v[6] + v[7]));
    #pragma unroll
    for (int o = 16; o; o >>= 1) lsum += __shfl_xor_sync(0xffffffffu, lsum, o);
    if (lane == 0) red[wid] = lsum;
    __syncthreads();
    if (tid == 0) {
        float t = 0.f;
        #pragma unroll
        for (int i = 0; i < 8; i++) t += red[i];
        red[0] = 1.0f / t;
    }
    __syncthreads();
    const float inv = red[0];

    float4* orow4 = (float4*)(att + (size_t)r * N_);
    __half2* hrow2 = (__half2*)(g_att_h + (size_t)r * N_);
    float4 o0 = make_float4(v[0] * inv, v[1] * inv, v[2] * inv, v[3] * inv);
    float4 o1 = make_float4(v[4] * inv, v[5] * inv, v[6] * inv, v[7] * inv);
    orow4[m4a] = o0;
    orow4[m4b] = o1;
    hrow2[m4a * 2    ] = __floats2half2_rn(o0.x, o0.y);
    hrow2[m4a * 2 + 1] = __floats2half2_rn(o0.z, o0.w);
    hrow2[m4b * 2    ] = __floats2half2_rn(o1.x, o1.y);
    hrow2[m4b * 2 + 1] = __floats2half2_rn(o1.z, o1.w);
}

// ---------------------------------------------------------------------------
// Kernel 4: h_prime = attention @ Wh, fp16 m16n8k16 with FP16 ACCUMULATORS
//   (2x rate on the legacy mma path), promoted to f32 every 4 K-chunks (256 k).
//   Tile 128x128, K-chunk 64, 3-stage cp.async ring.
// ---------------------------------------------------------------------------
#define KCHUNK 64
#define HSTRIDE 72                        // A smem row: 64 fp16 + 8 pad (144 B)
#define BSTRIDE_H 136                     // B smem row: 128 fp16 + 8 pad (272 B)
#define A_ELEMS (128 * HSTRIDE)           // 9216
#define STAGE_H (A_ELEMS + KCHUNK * BSTRIDE_H)   // 17920 fp16
#define K4_STAGES 3
#define SMEM_BYTES_K4 (K4_STAGES * STAGE_H * 2)   // 107520 B

__device__ __forceinline__ void k4_load_stage(__half* stage,
                                              const __half* A,
                                              const __half* Bw,
                                              int k0, int tid) {
    __half* As = stage;
    __half* Bs = stage + A_ELEMS;
    #pragma unroll
    for (int i = 0; i < 4; i++) {                 // A: 128 rows x 8 x 16B
        int flat = tid + i * 256, row = flat >> 3, c = flat & 7;
        cp16(&As[row * HSTRIDE + c * 8], A + (size_t)row * N_ + k0 + c * 8);
    }
    #pragma unroll
    for (int i = 0; i < 4; i++) {                 // B: 64 rows x 16 x 16B
        int flat = tid + i * 256, kr = flat >> 4, c = flat & 15;
        cp16(&Bs[kr * BSTRIDE_H + c * 8], Bw + (size_t)(k0 + kr) * F_ + c * 8);
    }
}

__global__ __launch_bounds__(256, 2) void k_gemm_av_f16(const float* __restrict__ h,
                                                        float* __restrict__ out) {
    extern __shared__ __half hsm[];
    const int bz = blockIdx.z;
    const int bx = blockIdx.x;   // 0..1 (n tile of 128)
    const int by = blockIdx.y;   // 0..15 (m tile of 128)
    const int tid = threadIdx.x;
    const int lane = tid & 31, wid = tid >> 5;
    const int warp_m = wid & 3, warp_n = wid >> 2;
    const int gid = lane >> 2, tig = lane & 3;

    const __half* A  = g_att_h + (size_t)bz * N_ * N_ + (size_t)(by * 128) * N_;
    const __half* Bw = g_Whh  + (size_t)bz * N_ * F_ + bx * 128;

    float    facc[2][8][4];     // f32 running sums (promoted)
    uint32_t acc16[2][8][2];    // f16x2 accumulators (reset each segment)
    #pragma unroll
    for (int mt = 0; mt < 2; mt++)
        #pragma unroll
        for (int j = 0; j < 8; j++) {
            #pragma unroll
            for (int q = 0; q < 4; q++) facc[mt][j][q] = 0.f;
            acc16[mt][j][0] = 0u; acc16[mt][j][1] = 0u;
        }

    // prologue: stages 0,1 = chunks 0,1
    k4_load_stage(hsm,           A, Bw, 0,      tid); cp_commit();
    k4_load_stage(hsm + STAGE_H, A, Bw, KCHUNK, tid); cp_commit();

    // ldmatrix lane offsets
    const int a_mat = lane >> 3, a_r = lane & 7;
    const int a_row_off = ((a_mat & 1) << 3) + a_r;
    const int a_k_off   = (a_mat >> 1) << 3;
    const int b_k_lane  = lane & 15;
    const int b_n_half  = (lane >> 4) << 3;

    const int NT = N_ / KCHUNK;   // 32
    int s = 0;
    for (int kt = 0; kt < NT; kt++) {
        cp_wait<1>();
        __syncthreads();

        if (kt + 2 < NT) {
            int sn = s + 2; if (sn >= K4_STAGES) sn -= K4_STAGES;
            k4_load_stage(hsm + sn * STAGE_H, A, Bw, (kt + 2) * KCHUNK, tid);
        }
        cp_commit();

        const __half* As = hsm + s * STAGE_H;
        const __half* Bs = As + A_ELEMS;

        #pragma unroll
        for (int kk = 0; kk < KCHUNK; kk += 16) {
            uint32_t af[2][4];
            #pragma unroll
            for (int mt = 0; mt < 2; mt++) {
                const __half* p =
                    As + (warp_m * 32 + mt * 16 + a_row_off) * HSTRIDE + kk + a_k_off;
                ldsm_x4(af[mt][0], af[mt][1], af[mt][2], af[mt][3], p);
            }
            uint32_t bf[8][2];
            #pragma unroll
            for (int jp = 0; jp < 4; jp++) {
                const __half* p =
                    Bs + (kk + b_k_lane) * BSTRIDE_H + warp_n * 64 + jp * 16 + b_n_half;
                ldsm_x4_t(bf[2*jp][0], bf[2*jp][1], bf[2*jp+1][0], bf[2*jp+1][1], p);
            }
            #pragma unroll
            for (int mt = 0; mt < 2; mt++)
                #pragma unroll
                for (int j = 0; j < 8; j++)
                    mma_f16(acc16[mt][j], af[mt], bf[j]);
        }

        // promote f16 -> f32 every 4 chunks (256 k-adds per segment)
        if (((kt + 1) & 3) == 0) {
            #pragma unroll
            for (int mt = 0; mt < 2; mt++)
                #pragma unroll
                for (int j = 0; j < 8; j++) {
                    float2 p0 = __half22float2(*(__half2*)&acc16[mt][j][0]);
                    float2 p1 = __half22float2(*(__half2*)&acc16[mt][j][1]);
                    facc[mt][j][0] += p0.x; facc[mt][j][1] += p0.y;
                    facc[mt][j][2] += p1.x; facc[mt][j][3] += p1.y;
                    acc16[mt][j][0] = 0u; acc16[mt][j][1] = 0u;
                }
        }

        if (++s >= K4_STAGES) s = 0;
        __syncthreads();
    }

    // epilogue: out = h + elu(h_prime)
    const size_t base = (size_t)bz * N_ * F_;
    #pragma unroll
    for (int mt = 0; mt < 2; mt++) {
        #pragma unroll
        for (int j = 0; j < 8; j++) {
            const int m0 = by * 128 + warp_m * 32 + mt * 16 + gid;
            const int n  = bx * 128 + warp_n * 64 + j * 8 + tig * 2;
            {
                const size_t idx = base + (size_t)m0 * F_ + n;
                float c0 = facc[mt][j][0], c1 = facc[mt][j][1];
                float e0 = c0 > 0.f ? c0 : expm1f(c0);
                float e1 = c1 > 0.f ? c1 : expm1f(c1);
                float2 hv = *(const float2*)(h + idx);
                *(float2*)(out + idx) = make_float2(hv.x + e0, hv.y + e1);
            }
            {
                const size_t idx = base + (size_t)(m0 + 8) * F_ + n;
                float c2 = facc[mt][j][2], c3 = facc[mt][j][3];
                float e2 = c2 > 0.f ? c2 : expm1f(c2);
                float e3 = c3 > 0.f ? c3 : expm1f(c3);
                float2 hv = *(const float2*)(h + idx);
                *(float2*)(out + idx) = make_float2(hv.x + e2, hv.y + e3);
            }
        }
    }
}

// ---------------------------------------------------------------------------
extern "C" void kernel_launch(void* const* d_in, const int* in_sizes, int n_in,
                              void* d_out, int out_size) {
    const float* h   = (const float*)d_in[0];
    const int*   adj = (const int*)  d_in[1];
    const float* W   = (const float*)d_in[2];
    const float* a   = (const float*)d_in[3];
    float* out = (float*)d_out;
    float* att = out + OUT_ELEMS;

    cudaFuncSetAttribute(k_gemm_wh,     cudaFuncAttributeMaxDynamicSharedMemorySize, SMEM_BYTES_K1);
    cudaFuncSetAttribute(k_gemm_av_f16, cudaFuncAttributeMaxDynamicSharedMemorySize, SMEM_BYTES_K4);

    // Round-9 schedule (the proven one): fork only k_gemm_wh; k4 runs full-grid.
    cudaStream_t s2;
    cudaStreamCreateWithFlags(&s2, cudaStreamNonBlocking);
    cudaEvent_t eFork, eJoin;
    cudaEventCreateWithFlags(&eFork, cudaEventDisableTiming);
    cudaEventCreateWithFlags(&eJoin, cudaEventDisableTiming);

    cudaEventRecord(eFork, 0);
    cudaStreamWaitEvent(s2, eFork, 0);
    // side branch: 1. Whh(fp16) = h @ W  (independent of score path)
    k_gemm_wh<<<dim3(2, ROWS / 128), 256, SMEM_BYTES_K1, s2>>>(h, W);
    cudaEventRecord(eJoin, s2);

    // main branch (critical path):
    k_wa<<<F_ / 8, 256>>>(W, a);
    k_rowdots<<<ROWS / 8, 256>>>(h);
    k_softmax<<<ROWS, 256>>>(adj, att);

    // join, then 4. h_prime = attention @ Wh ; out = h + elu(h_prime)
    cudaStreamWaitEvent(0, eJoin, 0);
    k_gemm_av_f16<<<dim3(2, N_ / 128, B_), 256, SMEM_BYTES_K4>>>(h, out);
}

// round 12
// speedup vs baseline: 1.2612x; 1.0662x over previous
#include <cuda_runtime.h>
#include <cuda_bf16.h>
#include <cuda_fp16.h>
#include <math.h>
#include <stdint.h>

// Problem constants
#define B_  8
#define N_  2048
#define F_  256
#define ROWS (B_ * N_)            // 16384
#define OUT_ELEMS ((size_t)B_ * N_ * F_)   // 4,194,304

// Scratch (device globals — no allocation allowed)
__device__ __half g_Whh[(size_t)B_ * N_ * F_];        // 8 MB fp16 [b][node m][feat f]
__device__ __half g_att_h[(size_t)B_ * N_ * N_];      // 67 MB fp16 [b][n][m]
__device__ __align__(16) float g_e1[ROWS];
__device__ __align__(16) float g_e2[ROWS];
__device__ __align__(16) float g_w1[F_];
__device__ __align__(16) float g_w2[F_];

// ---------------------------------------------------------------------------
// MMA / ldmatrix / cp.async helpers
// ---------------------------------------------------------------------------
__device__ __forceinline__ void mma_tf32(float* c, const uint32_t* a, const uint32_t* b) {
    asm volatile(
        "mma.sync.aligned.m16n8k8.row.col.f32.tf32.tf32.f32 "
        "{%0,%1,%2,%3}, {%4,%5,%6,%7}, {%8,%9}, {%0,%1,%2,%3};\n"
        : "+f"(c[0]), "+f"(c[1]), "+f"(c[2]), "+f"(c[3])
        : "r"(a[0]), "r"(a[1]), "r"(a[2]), "r"(a[3]), "r"(b[0]), "r"(b[1]));
}

// fp16 inputs, f32 accumulators (full-rate; round-11 showed f16-accum is NOT faster)
__device__ __forceinline__ void mma_f16_f32(float* c, const uint32_t* a, const uint32_t* b) {
    asm volatile(
        "mma.sync.aligned.m16n8k16.row.col.f32.f16.f16.f32 "
        "{%0,%1,%2,%3}, {%4,%5,%6,%7}, {%8,%9}, {%0,%1,%2,%3};\n"
        : "+f"(c[0]), "+f"(c[1]), "+f"(c[2]), "+f"(c[3])
        : "r"(a[0]), "r"(a[1]), "r"(a[2]), "r"(a[3]), "r"(b[0]), "r"(b[1]));
}

__device__ __forceinline__ void ldsm_x4(uint32_t& r0, uint32_t& r1, uint32_t& r2, uint32_t& r3,
                                        const void* p) {
    uint32_t a = (uint32_t)__cvta_generic_to_shared(p);
    asm volatile("ldmatrix.sync.aligned.m8n8.x4.shared.b16 {%0,%1,%2,%3}, [%4];"
                 : "=r"(r0), "=r"(r1), "=r"(r2), "=r"(r3) : "r"(a));
}
__device__ __forceinline__ void ldsm_x4_t(uint32_t& r0, uint32_t& r1, uint32_t& r2, uint32_t& r3,
                                          const void* p) {
    uint32_t a = (uint32_t)__cvta_generic_to_shared(p);
    asm volatile("ldmatrix.sync.aligned.m8n8.x4.trans.shared.b16 {%0,%1,%2,%3}, [%4];"
                 : "=r"(r0), "=r"(r1), "=r"(r2), "=r"(r3) : "r"(a));
}

__device__ __forceinline__ void cp16(void* dst, const void* src) {
    uint32_t d = (uint32_t)__cvta_generic_to_shared(dst);
    asm volatile("cp.async.cg.shared.global [%0], [%1], 16;\n" :: "r"(d), "l"(src));
}
__device__ __forceinline__ void cp_commit() {
    asm volatile("cp.async.commit_group;\n");
}
template<int NPEND> __device__ __forceinline__ void cp_wait() {
    asm volatile("cp.async.wait_group %0;\n" :: "n"(NPEND));
}

// ---------------------------------------------------------------------------
// Kernel 0: w1[r] = W[r,:]·a[:F],  w2[r] = W[r,:]·a[F:]   (W @ a, row dots)
// ---------------------------------------------------------------------------
__global__ void k_wa(const float* __restrict__ W, const float* __restrict__ a) {
    const int r = (blockIdx.x * blockDim.x + threadIdx.x) >> 5;   // 0..255
    const int lane = threadIdx.x & 31;
    if (r >= F_) return;
    const float* row = W + (size_t)r * F_;
    float s1 = 0.f, s2 = 0.f;
    #pragma unroll
    for (int f = lane; f < F_; f += 32) {
        float w = row[f];
        s1 = fmaf(w, a[f],      s1);
        s2 = fmaf(w, a[F_ + f], s2);
    }
    #pragma unroll
    for (int o = 16; o; o >>= 1) {
        s1 += __shfl_xor_sync(0xffffffffu, s1, o);
        s2 += __shfl_xor_sync(0xffffffffu, s2, o);
    }
    if (lane == 0) { g_w1[r] = s1; g_w2[r] = s2; }
}

// ---------------------------------------------------------------------------
// Kernel E: e1[r] = h[r,:]·w1, e2[r] = h[r,:]·w2   (one warp per row, exact)
// ---------------------------------------------------------------------------
__global__ void k_rowdots(const float* __restrict__ h) {
    const int gwarp = (blockIdx.x * blockDim.x + threadIdx.x) >> 5;
    const int lane = threadIdx.x & 31;
    if (gwarp >= ROWS) return;
    const float4* row = (const float4*)(h + (size_t)gwarp * F_);
    const float4* w1v = (const float4*)g_w1;
    const float4* w2v = (const float4*)g_w2;
    float s1 = 0.f, s2 = 0.f;
    #pragma unroll
    for (int f4 = lane; f4 < F_ / 4; f4 += 32) {
        float4 v = row[f4], w1 = w1v[f4], w2 = w2v[f4];
        s1 = fmaf(v.x, w1.x, fmaf(v.y, w1.y, fmaf(v.z, w1.z, fmaf(v.w, w1.w, s1))));
        s2 = fmaf(v.x, w2.x, fmaf(v.y, w2.y, fmaf(v.z, w2.z, fmaf(v.w, w2.w, s2))));
    }
    #pragma unroll
    for (int o = 16; o; o >>= 1) {
        s1 += __shfl_xor_sync(0xffffffffu, s1, o);
        s2 += __shfl_xor_sync(0xffffffffu, s2, o);
    }
    if (lane == 0) { g_e1[gwarp] = s1; g_e2[gwarp] = s2; }
}

// ---------------------------------------------------------------------------
// Kernel 1: Whh(fp16) = h @ W via single-pass TF32 MMA (tile 128x128x32).
// ---------------------------------------------------------------------------
#define STAGE_FLOATS 8960
#define A_OFF 0
#define B_OFF 4608
#define SMEM_BYTES_K1 (2 * STAGE_FLOATS * 4)   // 71680

__global__ __launch_bounds__(256, 2) void k_gemm_wh(const float* __restrict__ h,
                                                    const float* __restrict__ W) {
    extern __shared__ float dsm[];
    const int bx = blockIdx.x;
    const int by = blockIdx.y;
    const int tid = threadIdx.x;
    const int lane = tid & 31, wid = tid >> 5;
    const int warp_m = wid & 3, warp_n = wid >> 2;
    const int gid = lane >> 2, tig = lane & 3;

    const float* A  = h + (size_t)(by * 128) * F_;
    const float* Bg = W + bx * 128;

    float acc[2][8][4];
    #pragma unroll
    for (int mt = 0; mt < 2; mt++)
        #pragma unroll
        for (int j = 0; j < 8; j++)
            #pragma unroll
            for (int q = 0; q < 4; q++) acc[mt][j][q] = 0.f;

    {
        float* As = dsm + A_OFF;
        float* Bs = dsm + B_OFF;
        #pragma unroll
        for (int i = 0; i < 4; i++) {
            int flat = tid + i * 256, row = flat >> 3, c4 = flat & 7;
            cp16(&As[row * 36 + c4 * 4], A + (size_t)row * F_ + c4 * 4);
        }
        #pragma unroll
        for (int i = 0; i < 4; i++) {
            int flat = tid + i * 256, kr = flat >> 5, c4 = flat & 31;
            cp16(&Bs[kr * 136 + c4 * 4], Bg + (size_t)kr * F_ + c4 * 4);
        }
        cp_commit();
    }

    const int NT = F_ / 32;   // 8
    for (int kt = 0; kt < NT; kt++) {
        const int cur = kt & 1;
        if (kt + 1 < NT) {
            const int k0 = (kt + 1) * 32;
            float* As = dsm + (1 - cur) * STAGE_FLOATS + A_OFF;
            float* Bs = dsm + (1 - cur) * STAGE_FLOATS + B_OFF;
            #pragma unroll
            for (int i = 0; i < 4; i++) {
                int flat = tid + i * 256, row = flat >> 3, c4 = flat & 7;
                cp16(&As[row * 36 + c4 * 4], A + (size_t)row * F_ + k0 + c4 * 4);
            }
            #pragma unroll
            for (int i = 0; i < 4; i++) {
                int flat = tid + i * 256, kr = flat >> 5, c4 = flat & 31;
                cp16(&Bs[kr * 136 + c4 * 4], Bg + (size_t)(k0 + kr) * F_ + c4 * 4);
            }
            cp_commit();
            cp_wait<1>();
        } else {
            cp_wait<0>();
        }
        __syncthreads();

        const float* As = dsm + cur * STAGE_FLOATS + A_OFF;
        const float* Bs = dsm + cur * STAGE_FLOATS + B_OFF;

        #pragma unroll
        for (int kk = 0; kk < 32; kk += 8) {
            uint32_t afr[2][4];
            #pragma unroll
            for (int mt = 0; mt < 2; mt++) {
                int r = warp_m * 32 + mt * 16 + gid;
                afr[mt][0] = __float_as_uint(As[ r      * 36 + kk + tig    ]);
                afr[mt][1] = __float_as_uint(As[(r + 8) * 36 + kk + tig    ]);
                afr[mt][2] = __float_as_uint(As[ r      * 36 + kk + tig + 4]);
                afr[mt][3] = __float_as_uint(As[(r + 8) * 36 + kk + tig + 4]);
            }
            uint32_t bfr[8][2];
            #pragma unroll
            for (int j = 0; j < 8; j++) {
                int n = warp_n * 64 + j * 8 + gid;
                bfr[j][0] = __float_as_uint(Bs[(kk + tig    ) * 136 + n]);
                bfr[j][1] = __float_as_uint(Bs[(kk + tig + 4) * 136 + n]);
            }
            #pragma unroll
            for (int mt = 0; mt < 2; mt++)
                #pragma unroll
                for (int j = 0; j < 8; j++)
                    mma_tf32(acc[mt][j], afr[mt], bfr[j]);
        }
        __syncthreads();
    }

    #pragma unroll
    for (int mt = 0; mt < 2; mt++) {
        #pragma unroll
        for (int j = 0; j < 8; j++) {
            const int m0 = by * 128 + warp_m * 32 + mt * 16 + gid;
            const int n  = bx * 128 + warp_n * 64 + j * 8 + tig * 2;
            *(__half2*)(g_Whh + (size_t) m0      * F_ + n) =
                __floats2half2_rn(acc[mt][j][0], acc[mt][j][1]);
            *(__half2*)(g_Whh + (size_t)(m0 + 8) * F_ + n) =
                __floats2half2_rn(acc[mt][j][2], acc[mt][j][3]);
        }
    }
}

// ---------------------------------------------------------------------------
// Kernel 3: masked leaky-relu + softmax — register-resident.
// Writes fp32 attention to d_out AND fp16 copy to g_att_h.
// ---------------------------------------------------------------------------
__global__ __launch_bounds__(256) void k_softmax(const int* __restrict__ adj,
                                                 float* __restrict__ att) {
    const int r = blockIdx.x;
    const int b = r >> 11;
    __shared__ float red[8];

    const int4*   arow4 = (const int4*)(adj + (size_t)r * N_);
    const float4* e2b4  = (const float4*)(g_e2 + b * N_);
    const float E1 = g_e1[r];
    const int tid = threadIdx.x, lane = tid & 31, wid = tid >> 5;

    const int m4a = tid;
    const int m4b = tid + 256;

    int4   ad0 = arow4[m4a], ad1 = arow4[m4b];
    float4 e20 = e2b4[m4a],  e21 = e2b4[m4b];

    float v[8];
    {
        float x;
        x = E1 + e20.x; x = x > 0.f ? x : 0.2f * x; v[0] = ad0.x > 0 ? __expf(x) : 0.f;
        x = E1 + e20.y; x = x > 0.f ? x : 0.2f * x; v[1] = ad0.y > 0 ? __expf(x) : 0.f;
        x = E1 + e20.z; x = x > 0.f ? x : 0.2f * x; v[2] = ad0.z > 0 ? __expf(x) : 0.f;
        x = E1 + e20.w; x = x > 0.f ? x : 0.2f * x; v[3] = ad0.w > 0 ? __expf(x) : 0.f;
        x = E1 + e21.x; x = x > 0.f ? x : 0.2f * x; v[4] = ad1.x > 0 ? __expf(x) : 0.f;
        x = E1 + e21.y; x = x > 0.f ? x : 0.2f * x; v[5] = ad1.y > 0 ? __expf(x) : 0.f;
        x = E1 + e21.z; x = x > 0.f ? x : 0.2f * x; v[6] = ad1.z > 0 ? __expf(x) : 0.f;
        x = E1 + e21.w; x = x > 0.f ? x : 0.2f * x; v[7] = ad1.w > 0 ? __expf(x) : 0.f;
    }
    float lsum = ((v[0] + v[1]) + (v[2] + v[3])) + ((v[4] + v[5]) + (v[6] + v[7]));
    #pragma unroll
    for (int o = 16; o; o >>= 1) lsum += __shfl_xor_sync(0xffffffffu, lsum, o);
    if (lane == 0) red[wid] = lsum;
    __syncthreads();
    if (tid == 0) {
        float t = 0.f;
        #pragma unroll
        for (int i = 0; i < 8; i++) t += red[i];
        red[0] = 1.0f / t;
    }
    __syncthreads();
    const float inv = red[0];

    float4* orow4 = (float4*)(att + (size_t)r * N_);
    __half2* hrow2 = (__half2*)(g_att_h + (size_t)r * N_);
    float4 o0 = make_float4(v[0] * inv, v[1] * inv, v[2] * inv, v[3] * inv);
    float4 o1 = make_float4(v[4] * inv, v[5] * inv, v[6] * inv, v[7] * inv);
    orow4[m4a] = o0;
    orow4[m4b] = o1;
    hrow2[m4a * 2    ] = __floats2half2_rn(o0.x, o0.y);
    hrow2[m4a * 2 + 1] = __floats2half2_rn(o0.z, o0.w);
    hrow2[m4b * 2    ] = __floats2half2_rn(o1.x, o1.y);
    hrow2[m4b * 2 + 1] = __floats2half2_rn(o1.z, o1.w);
}

// ---------------------------------------------------------------------------
// Kernel 4: h_prime = attention @ Wh, fp16 m16n8k16 with F32 ACCUMULATORS
//   (round-9 structure; fp16 inputs for precision). Tile 128x128, K-chunk 64,
//   3-stage cp.async ring, ONE barrier per chunk (top barrier covers both the
//   data-visibility and the stage-reuse hazard: load target (kt+2)%3 == stage
//   read at kt-1, and the barrier proves all warps finished iteration kt-1).
// ---------------------------------------------------------------------------
#define KCHUNK 64
#define HSTRIDE 72                        // A smem row: 64 fp16 + 8 pad (144 B)
#define BSTRIDE_H 136                     // B smem row: 128 fp16 + 8 pad (272 B)
#define A_ELEMS (128 * HSTRIDE)           // 9216
#define STAGE_H (A_ELEMS + KCHUNK * BSTRIDE_H)   // 17920 fp16
#define K4_STAGES 3
#define SMEM_BYTES_K4 (K4_STAGES * STAGE_H * 2)   // 107520 B

__device__ __forceinline__ void k4_load_stage(__half* stage,
                                              const __half* A,
                                              const __half* Bw,
                                              int k0, int tid) {
    __half* As = stage;
    __half* Bs = stage + A_ELEMS;
    #pragma unroll
    for (int i = 0; i < 4; i++) {                 // A: 128 rows x 8 x 16B
        int flat = tid + i * 256, row = flat >> 3, c = flat & 7;
        cp16(&As[row * HSTRIDE + c * 8], A + (size_t)row * N_ + k0 + c * 8);
    }
    #pragma unroll
    for (int i = 0; i < 4; i++) {                 // B: 64 rows x 16 x 16B
        int flat = tid + i * 256, kr = flat >> 4, c = flat & 15;
        cp16(&Bs[kr * BSTRIDE_H + c * 8], Bw + (size_t)(k0 + kr) * F_ + c * 8);
    }
}

__global__ __launch_bounds__(256, 2) void k_gemm_av_f16(const float* __restrict__ h,
                                                        float* __restrict__ out) {
    extern __shared__ __half hsm[];
    const int bz = blockIdx.z;
    const int bx = blockIdx.x;   // 0..1 (n tile of 128)
    const int by = blockIdx.y;   // 0..15 (m tile of 128)
    const int tid = threadIdx.x;
    const int lane = tid & 31, wid = tid >> 5;
    const int warp_m = wid & 3, warp_n = wid >> 2;
    const int gid = lane >> 2, tig = lane & 3;

    const __half* A  = g_att_h + (size_t)bz * N_ * N_ + (size_t)(by * 128) * N_;
    const __half* Bw = g_Whh  + (size_t)bz * N_ * F_ + bx * 128;

    float acc[2][8][4];
    #pragma unroll
    for (int mt = 0; mt < 2; mt++)
        #pragma unroll
        for (int j = 0; j < 8; j++)
            #pragma unroll
            for (int q = 0; q < 4; q++) acc[mt][j][q] = 0.f;

    // prologue: stages 0,1 = chunks 0,1
    k4_load_stage(hsm,           A, Bw, 0,      tid); cp_commit();
    k4_load_stage(hsm + STAGE_H, A, Bw, KCHUNK, tid); cp_commit();

    // ldmatrix lane offsets
    const int a_mat = lane >> 3, a_r = lane & 7;
    const int a_row_off = ((a_mat & 1) << 3) + a_r;
    const int a_k_off   = (a_mat >> 1) << 3;
    const int b_k_lane  = lane & 15;
    const int b_n_half  = (lane >> 4) << 3;

    const int NT = N_ / KCHUNK;   // 32
    int s = 0;
    for (int kt = 0; kt < NT; kt++) {
        cp_wait<1>();            // chunk kt resident (all but newest group)
        __syncthreads();         // visibility + all warps done with iter kt-1

        if (kt + 2 < NT) {
            int sn = s + 2; if (sn >= K4_STAGES) sn -= K4_STAGES;
            k4_load_stage(hsm + sn * STAGE_H, A, Bw, (kt + 2) * KCHUNK, tid);
        }
        cp_commit();

        const __half* As = hsm + s * STAGE_H;
        const __half* Bs = As + A_ELEMS;

        #pragma unroll
        for (int kk = 0; kk < KCHUNK; kk += 16) {
            uint32_t af[2][4];
            #pragma unroll
            for (int mt = 0; mt < 2; mt++) {
                const __half* p =
                    As + (warp_m * 32 + mt * 16 + a_row_off) * HSTRIDE + kk + a_k_off;
                ldsm_x4(af[mt][0], af[mt][1], af[mt][2], af[mt][3], p);
            }
            uint32_t bf[8][2];
            #pragma unroll
            for (int jp = 0; jp < 4; jp++) {
                const __half* p =
                    Bs + (kk + b_k_lane) * BSTRIDE_H + warp_n * 64 + jp * 16 + b_n_half;
                ldsm_x4_t(bf[2*jp][0], bf[2*jp][1], bf[2*jp+1][0], bf[2*jp+1][1], p);
            }
            #pragma unroll
            for (int mt = 0; mt < 2; mt++)
                #pragma unroll
                for (int j = 0; j < 8; j++)
                    mma_f16_f32(acc[mt][j], af[mt], bf[j]);
        }
        if (++s >= K4_STAGES) s = 0;
        // no trailing barrier: next iteration's top barrier protects stage reuse
    }

    // epilogue: out = h + elu(h_prime)
    const size_t base = (size_t)bz * N_ * F_;
    #pragma unroll
    for (int mt = 0; mt < 2; mt++) {
        #pragma unroll
        for (int j = 0; j < 8; j++) {
            const int m0 = by * 128 + warp_m * 32 + mt * 16 + gid;
            const int n  = bx * 128 + warp_n * 64 + j * 8 + tig * 2;
            {
                const size_t idx = base + (size_t)m0 * F_ + n;
                float c0 = acc[mt][j][0], c1 = acc[mt][j][1];
                float e0 = c0 > 0.f ? c0 : expm1f(c0);
                float e1 = c1 > 0.f ? c1 : expm1f(c1);
                float2 hv = *(const float2*)(h + idx);
                *(float2*)(out + idx) = make_float2(hv.x + e0, hv.y + e1);
            }
            {
                const size_t idx = base + (size_t)(m0 + 8) * F_ + n;
                float c2 = acc[mt][j][2], c3 = acc[mt][j][3];
                float e2 = c2 > 0.f ? c2 : expm1f(c2);
                float e3 = c3 > 0.f ? c3 : expm1f(c3);
                float2 hv = *(const float2*)(h + idx);
                *(float2*)(out + idx) = make_float2(hv.x + e2, hv.y + e3);
            }
        }
    }
}

// ---------------------------------------------------------------------------
extern "C" void kernel_launch(void* const* d_in, const int* in_sizes, int n_in,
                              void* d_out, int out_size) {
    const float* h   = (const float*)d_in[0];
    const int*   adj = (const int*)  d_in[1];
    const float* W   = (const float*)d_in[2];
    const float* a   = (const float*)d_in[3];
    float* out = (float*)d_out;
    float* att = out + OUT_ELEMS;

    cudaFuncSetAttribute(k_gemm_wh,     cudaFuncAttributeMaxDynamicSharedMemorySize, SMEM_BYTES_K1);
    cudaFuncSetAttribute(k_gemm_av_f16, cudaFuncAttributeMaxDynamicSharedMemorySize, SMEM_BYTES_K4);

    // Round-9 schedule (proven): fork only k_gemm_wh; k4 runs full-grid.
    cudaStream_t s2;
    cudaStreamCreateWithFlags(&s2, cudaStreamNonBlocking);
    cudaEvent_t eFork, eJoin;
    cudaEventCreateWithFlags(&eFork, cudaEventDisableTiming);
    cudaEventCreateWithFlags(&eJoin, cudaEventDisableTiming);

    cudaEventRecord(eFork, 0);
    cudaStreamWaitEvent(s2, eFork, 0);
    // side branch: 1. Whh(fp16) = h @ W  (independent of score path)
    k_gemm_wh<<<dim3(2, ROWS / 128), 256, SMEM_BYTES_K1, s2>>>(h, W);
    cudaEventRecord(eJoin, s2);

    // main branch (critical path):
    k_wa<<<F_ / 8, 256>>>(W, a);
    k_rowdots<<<ROWS / 8, 256>>>(h);
    k_softmax<<<ROWS, 256>>>(adj, att);

    // join, then 4. h_prime = attention @ Wh ; out = h + elu(h_prime)
    cudaStreamWaitEvent(0, eJoin, 0);
    k_gemm_av_f16<<<dim3(2, N_ / 128, B_), 256, SMEM_BYTES_K4>>>(h, out);
}